// round 16
// baseline (speedup 1.0000x reference)
#include <cuda_runtime.h>
#include <cuda_bf16.h>
#include <cstdint>

#define BB 32
#define SS 100
#define TT 100
#define EE 128
#define HH 256
#define VV 32000
#define G3 (3*HH)
#define TV (TT*VV)
#define GRIDN 148
#define BST 36      // Xih staging stride (setup only)
#define XST 649     // P1 x staging stride [b][k]
#define EST 193     // encoder weight smem stride
#define NLC 140     // logits CTAs

typedef unsigned long long ull;

__device__ float g_Xih[BB*SS*G3];
__device__ float g_enc_outs[BB*SS*HH];
__device__ float g_enc_part[BB*SS];
__device__ float g_h[2][BB*HH];
__device__ float g_hT[HH*BB];            // h transposed [j][b], written by P1
__device__ float g_hx[BB*HH];
__device__ float g_ctx[BB*HH];
__device__ ull g_amax[2][BB];
__device__ unsigned g_ctr;
__device__ unsigned g_ectr[BB];
__device__ float g_oWT[(size_t)HH*VV];
__device__ float g_eWihT[EE*G3];

__device__ __forceinline__ float sigf(float x) { return 1.0f / (1.0f + expf(-x)); }
__device__ __forceinline__ unsigned fkey(float f) {
    unsigned u = __float_as_uint(f);
    return (u & 0x80000000u) ? ~u : (u | 0x80000000u);
}
__device__ __forceinline__ ull pk2(float x, float y) {
    ull r; asm("mov.b64 %0, {%1, %2};" : "=l"(r) : "f"(x), "f"(y)); return r;
}
__device__ __forceinline__ void upk2(ull p, float &x, float &y) {
    asm("mov.b64 {%0, %1}, %2;" : "=f"(x), "=f"(y) : "l"(p));
}
__device__ __forceinline__ ull fma2(ull a, ull b, ull c) {
    ull d; asm("fma.rn.f32x2 %0, %1, %2, %3;" : "=l"(d) : "l"(a), "l"(b), "l"(c)); return d;
}

// grid barrier: tight poll first, nanosleep backoff later
__device__ __forceinline__ void gbar(int &nbar) {
    __syncthreads();
    if (threadIdx.x == 0) {
        __threadfence();
        unsigned tgt = (unsigned)(nbar + 1) * GRIDN;
        atomicAdd(&g_ctr, 1u);
        unsigned iter = 0;
        while (true) {
            unsigned v;
            asm volatile("ld.acquire.gpu.global.u32 %0, [%1];" : "=r"(v) : "l"(&g_ctr));
            if (v >= tgt) break;
            ++iter;
            if (iter > 8000000u) break;
            if (iter > 2048u) __nanosleep(64);
        }
        __threadfence();
    }
    nbar++;
    __syncthreads();
}

__device__ __forceinline__ void minibar(int grp, int step) {
    __syncthreads();
    if (threadIdx.x == 0) {
        __threadfence();
        unsigned tgt = (unsigned)(step + 1) * 4u;
        atomicAdd(&g_ectr[grp], 1u);
        unsigned iter = 0;
        while (true) {
            unsigned v;
            asm volatile("ld.acquire.gpu.global.u32 %0, [%1];" : "=r"(v) : "l"(&g_ectr[grp]));
            if (v >= tgt) break;
            if (++iter > 20000000u) break;
        }
        __threadfence();
    }
    __syncthreads();
}

__global__ void k_reset() {
    g_ctr = 0u;
    for (int i = 0; i < BB; i++) g_ectr[i] = 0u;
}

__device__ __forceinline__ float rsum256(float v, float* red) {
    int tid = threadIdx.x;
    red[tid] = v; __syncthreads();
    #pragma unroll
    for (int o = 128; o > 0; o >>= 1) { if (tid < o) red[tid] += red[tid + o]; __syncthreads(); }
    float r = red[0]; __syncthreads();
    return r;
}
__device__ __forceinline__ float rmax256(float v, float* red) {
    int tid = threadIdx.x;
    red[tid] = v; __syncthreads();
    #pragma unroll
    for (int o = 128; o > 0; o >>= 1) { if (tid < o) red[tid] = fmaxf(red[tid], red[tid + o]); __syncthreads(); }
    float r = red[0]; __syncthreads();
    return r;
}

__global__ void __launch_bounds__(256, 1)
mega(const int* __restrict__ ing, const float* __restrict__ emb,
     const float* __restrict__ eWih, const float* __restrict__ eWhh,
     const float* __restrict__ ebih, const float* __restrict__ ebhh,
     const float* __restrict__ dWih, const float* __restrict__ dWhh,
     const float* __restrict__ dbih, const float* __restrict__ dbhh,
     const float* __restrict__ aW, const float* __restrict__ ab,
     const float* __restrict__ oW, const float* __restrict__ ob,
     float* __restrict__ out)
{
    extern __shared__ float dyn[];
    float* wsm = dyn;
    float* buf = dyn + 3840;   // 128B-aligned

    __shared__ float S[8][2][32];
    __shared__ float S4[4][3][64];
    __shared__ float hs[HH];
    __shared__ float ebs[192];
    __shared__ float red[256];
    __shared__ float ws[128];
    __shared__ int   toks[BB];
    __shared__ ull   slots[BB];

    const int c = blockIdx.x, tid = threadIdx.x;
    const int w = tid >> 5, lane = tid & 31;
    const int tx = tid & 31, ty = tid >> 5;
    int nbar = 0;

    // ============ Phase A: zero h0 + transposes (oW, eWih) ============
    if (c == 0) for (int i = tid; i < BB*HH; i += 256) g_h[0][i] = 0.0f;
    {
        float* tbuf = buf;
        for (int tile = c; tile < 8096; tile += GRIDN) {
            __syncthreads();
            if (tile < 8000) {
                int vt = tile >> 3, kt = tile & 7;
                int v0 = vt*32, k0 = kt*32;
                #pragma unroll
                for (int i = 0; i < 4; i++) {
                    int vv = ty + 8*i;
                    tbuf[vv*33 + tx] = oW[(size_t)(v0+vv)*HH + k0 + tx];
                }
                __syncthreads();
                #pragma unroll
                for (int i = 0; i < 4; i++) {
                    int kk = ty + 8*i;
                    g_oWT[(size_t)(k0+kk)*VV + v0 + tx] = tbuf[tx*33 + kk];
                }
            } else {
                int tt = tile - 8000;
                int rt = tt >> 2, kt = tt & 3;
                int r0 = rt*32, k0 = kt*32;
                #pragma unroll
                for (int i = 0; i < 4; i++) {
                    int rr = ty + 8*i;
                    tbuf[rr*33 + tx] = eWih[(size_t)(r0+rr)*EE + k0 + tx];
                }
                __syncthreads();
                #pragma unroll
                for (int i = 0; i < 4; i++) {
                    int kk = ty + 8*i;
                    g_eWihT[(k0+kk)*G3 + r0 + tx] = tbuf[tx*33 + kk];
                }
            }
        }
    }
    gbar(nbar);

    // ============ Phase B: Xih GEMM (c<100) + encoder weights (c<128) ============
    if (c < 100) {
        int p0 = c*32;
        if (tid < 32) toks[tid] = ing[p0 + tid];
        __syncthreads();
        for (int idx = tid; idx < EE*32; idx += 256) {
            int p = idx >> 7, k = idx & 127;
            buf[k*BST + p] = emb[(size_t)toks[p]*EE + k];
        }
        __syncthreads();
        ull acc[3][16];
        #pragma unroll
        for (int g = 0; g < 3; g++) {
            float bi = ebih[tid + g*256];
            ull bv = pk2(bi, bi);
            #pragma unroll
            for (int j = 0; j < 16; j++) acc[g][j] = bv;
        }
        #pragma unroll 2
        for (int k = 0; k < EE; k++) {
            float w0 = g_eWihT[k*G3 + tid];
            float w1 = g_eWihT[k*G3 + 256 + tid];
            float w2 = g_eWihT[k*G3 + 512 + tid];
            ull W0 = pk2(w0, w0), W1 = pk2(w1, w1), W2 = pk2(w2, w2);
            const ulonglong2* xp = (const ulonglong2*)(buf + k*BST);
            #pragma unroll
            for (int i = 0; i < 8; i++) {
                ulonglong2 hv = xp[i];
                acc[0][2*i]   = fma2(W0, hv.x, acc[0][2*i]);
                acc[0][2*i+1] = fma2(W0, hv.y, acc[0][2*i+1]);
                acc[1][2*i]   = fma2(W1, hv.x, acc[1][2*i]);
                acc[1][2*i+1] = fma2(W1, hv.y, acc[1][2*i+1]);
                acc[2][2*i]   = fma2(W2, hv.x, acc[2][2*i]);
                acc[2][2*i+1] = fma2(W2, hv.y, acc[2][2*i+1]);
            }
        }
        #pragma unroll
        for (int g = 0; g < 3; g++) {
            int r = tid + g*256;
            #pragma unroll
            for (int j = 0; j < 16; j++) {
                float f0, f1;
                upk2(acc[g][j], f0, f1);
                g_Xih[(size_t)(p0 + 2*j)*G3 + r] = f0;
                g_Xih[(size_t)(p0 + 2*j + 1)*G3 + r] = f1;
            }
        }
    }
    __syncthreads();
    if (c < 128) {
        int part = c & 3;
        for (int idx = tid; idx < 192*64; idx += 256) {
            int k4 = idx & 63, r = idx >> 6;
            int g = r >> 6, jl = r & 63;
            float4 v = *(const float4*)(eWhh + (size_t)(g*256 + part*64 + jl)*HH + 4*k4);
            wsm[(4*k4+0)*EST + r] = v.x;
            wsm[(4*k4+1)*EST + r] = v.y;
            wsm[(4*k4+2)*EST + r] = v.z;
            wsm[(4*k4+3)*EST + r] = v.w;
        }
        for (int i = tid; i < 192; i += 256) {
            int g = i >> 6, jl = i & 63;
            ebs[i] = ebhh[g*256 + part*64 + jl];
        }
        if (tid < HH) hs[tid] = 0.0f;
    }
    gbar(nbar);

    // ============ Encoder: 32 groups x 4 CTAs ============
    if (c < 128) {
        int b = c >> 2, part = c & 3;
        for (int s = 0; s < SS; s++) {
            int jl = tid & 63, q = tid >> 6;
            float aR = 0.f, aZ = 0.f, aN = 0.f;
            const float* wp = wsm + (q*64)*EST;
            #pragma unroll 4
            for (int kk = 0; kk < 64; kk++) {
                float hv = hs[q*64 + kk];
                aR += wp[kk*EST + jl] * hv;
                aZ += wp[kk*EST + 64 + jl] * hv;
                aN += wp[kk*EST + 128 + jl] * hv;
            }
            S4[q][0][jl] = aR; S4[q][1][jl] = aZ; S4[q][2][jl] = aN;
            __syncthreads();
            if (tid < 64) {
                int j = part*64 + tid;
                float rs = S4[0][0][tid]+S4[1][0][tid]+S4[2][0][tid]+S4[3][0][tid];
                float zs = S4[0][1][tid]+S4[1][1][tid]+S4[2][1][tid]+S4[3][1][tid];
                float ns = S4[0][2][tid]+S4[1][2][tid]+S4[2][2][tid]+S4[3][2][tid];
                const float* gi = g_Xih + ((size_t)b*SS + s)*G3;
                float r = sigf(gi[j] + rs + ebs[tid]);
                float z = sigf(gi[HH + j] + zs + ebs[64 + tid]);
                float n = tanhf(gi[2*HH + j] + r*(ns + ebs[128 + tid]));
                float h2 = (1.0f - z)*n + z*hs[j];
                g_enc_outs[((size_t)b*SS + s)*HH + j] = h2;
                g_hx[b*HH + j] = h2;
                if (s == SS-1) g_h[0][b*HH + j] = h2;
            }
            minibar(b, s);
            if (tid < HH) hs[tid] = g_hx[b*HH + tid];
            __syncthreads();
        }
    }
    gbar(nbar);

    // ============ enc_part + decoder weight slice ============
    if (c < 128) {
        int j0 = 2*c;
        for (int g = tid; g < 3840; g += 256) {
            int jl = (g >= 1920) ? 1 : 0;
            int gg = g - jl*1920;
            int j = j0 + jl;
            int rl, k;
            if (gg < 640)       { rl = 0; k = gg; }
            else if (gg < 1280) { rl = 1; k = gg - 640; }
            else if (gg < 1664) { rl = 2; k = gg - 1280; }
            else                { rl = 3; k = gg - 1664; }
            float v;
            if (rl == 0)      v = (k < 384) ? dWih[(size_t)j*384 + k]          : dWhh[(size_t)j*HH + (k-384)];
            else if (rl == 1) v = (k < 384) ? dWih[(size_t)(256+j)*384 + k]    : dWhh[(size_t)(256+j)*HH + (k-384)];
            else if (rl == 2) v = dWih[(size_t)(512+j)*384 + k];
            else              v = dWhh[(size_t)(512+j)*HH + k];
            wsm[g] = v;
        }
    }
    {
        int gt = c*256 + tid;
        if (gt < BB*SS) {
            const float4* e4 = (const float4*)(g_enc_outs + (size_t)gt*HH);
            const float4* w4 = (const float4*)aW;
            float a0 = ab[0], a1=0,a2=0,a3=0;
            #pragma unroll 8
            for (int k = 0; k < HH/4; k++) {
                float4 e = e4[k]; float4 ww = __ldg(&w4[k]);
                a0 += e.x*ww.x; a1 += e.y*ww.y; a2 += e.z*ww.z; a3 += e.w*ww.w;
            }
            g_enc_part[gt] = (a0+a1)+(a2+a3);
        }
    }
    gbar(nbar);

    // ============ decoder ============
    static const int rowoff_[8] = {0,640,1280,1664,1920,2560,3200,3584};
    static const int s0row_[8] = {0,0,1,2,4,4,5,6};
    static const int s0k_[8]   = {0,480,320,160,0,480,320,160};
    static const int s0len_[8] = {480,160,320,224,480,160,320,224};
    static const int s1row_[8] = {0,1,2,3,4,5,6,7};
    static const int s1len_[8] = {0,320,160,256,0,320,160,256};

    // attention: 8 CTAs (c>=NLC), 4 batches each: b = i + 8*q
    auto do_attn = [&](const float* h) {
        int i = c - NLC;
        for (int q = 0; q < 4; q++) {
            int b = i + q*8;
            float p = h[b*HH + tid] * aW[HH + tid];
            float hw = rsum256(p, red);
            float sc = (tid < SS) ? (g_enc_part[b*SS + tid] + hw) : -1e30f;
            float mx = rmax256(sc, red);
            float e = (tid < SS) ? expf(sc - mx) : 0.0f;
            if (tid < 128) ws[tid] = (tid < SS) ? e : 0.0f;
            float inv = 1.0f / rsum256(e, red);
            __syncthreads();
            int j = tid;
            const float* eo = g_enc_outs + (size_t)b*SS*HH + j;
            float a0=0, a1=0;
            #pragma unroll 4
            for (int s = 0; s < SS; s += 2) {
                a0 += ws[s] * eo[(size_t)s*HH];
                a1 += ws[s+1] * eo[(size_t)(s+1)*HH];
            }
            g_ctx[b*HH + j] = (a0 + a1) * inv;
            __syncthreads();
        }
    };

    if (c >= NLC) do_attn(g_h[0]);
    gbar(nbar);

    for (int t = 0; t < TT; t++) {
        // -------- P1: GRU (c<128) --------
        if (c < 128) {
            if (tid < BB)
                toks[tid] = (t == 0) ? 1
                    : (int)(0xFFFFFFFFu - (unsigned)(g_amax[(t-1) & 1][tid] & 0xFFFFFFFFull));
            if (c == 0 && tid >= 32 && tid < 64) g_amax[t & 1][tid - 32] = 0ULL;
            __syncthreads();
            const float* hin = g_h[t & 1];
            {
                int b = tid >> 3, f = tid & 7;
                float* xr = buf + b*XST;
                #pragma unroll
                for (int i = 0; i < 4; i++) {
                    int k4 = f + 8*i;
                    float4 v = *(const float4*)(emb + (size_t)toks[b]*EE + 4*k4);
                    xr[4*k4+0]=v.x; xr[4*k4+1]=v.y; xr[4*k4+2]=v.z; xr[4*k4+3]=v.w;
                }
                #pragma unroll
                for (int i = 0; i < 8; i++) {
                    int k4 = f + 8*i;
                    float4 v = *(const float4*)(g_ctx + b*HH + 4*k4);
                    int o = 128 + 4*k4;
                    xr[o]=v.x; xr[o+1]=v.y; xr[o+2]=v.z; xr[o+3]=v.w;
                }
                #pragma unroll
                for (int i = 0; i < 8; i++) {
                    int k4 = f + 8*i;
                    float4 v = *(const float4*)(hin + b*HH + 4*k4);
                    int o = 384 + 4*k4;
                    xr[o]=v.x; xr[o+1]=v.y; xr[o+2]=v.z; xr[o+3]=v.w;
                }
            }
            __syncthreads();
            const float* xb = buf + lane*XST;
            {
                int r0 = s0row_[w], k0 = s0k_[w], l0 = s0len_[w];
                const float4* wv = (const float4*)(wsm + rowoff_[r0] + k0);
                int bo = (((r0 & 3) == 3) ? 384 : 0) + k0;
                float a0=0,a1=0,a2=0,a3=0;
                #pragma unroll 4
                for (int i = 0; i < l0/4; i++) {
                    float4 x = wv[i];
                    const float* xp = xb + bo + 4*i;
                    a0 += x.x*xp[0]; a1 += x.y*xp[1];
                    a2 += x.z*xp[2]; a3 += x.w*xp[3];
                }
                S[w][0][lane] = (a0+a1)+(a2+a3);
            }
            {
                int r1 = s1row_[w], l1 = s1len_[w];
                float acc = 0.0f;
                if (l1 > 0) {
                    const float4* wv = (const float4*)(wsm + rowoff_[r1]);
                    int bo = ((r1 & 3) == 3) ? 384 : 0;
                    float a0=0,a1=0,a2=0,a3=0;
                    #pragma unroll 4
                    for (int i = 0; i < l1/4; i++) {
                        float4 x = wv[i];
                        const float* xp = xb + bo + 4*i;
                        a0 += x.x*xp[0]; a1 += x.y*xp[1];
                        a2 += x.z*xp[2]; a3 += x.w*xp[3];
                    }
                    acc = (a0+a1)+(a2+a3);
                }
                S[w][1][lane] = acc;
            }
            __syncthreads();
            if (w == 0 || w == 4) {
                int jl = w >> 2, base = jl*4;
                int j = 2*c + jl, b = lane;
                float r_in = S[base+0][0][b] + S[base+1][0][b];
                float z_in = S[base+1][1][b] + S[base+2][0][b];
                float nx   = S[base+2][1][b] + S[base+3][0][b];
                float nh   = S[base+3][1][b];
                float r = sigf(r_in + dbih[j] + dbhh[j]);
                float z = sigf(z_in + dbih[HH + j] + dbhh[HH + j]);
                float n = tanhf(nx + dbih[2*HH + j] + r*(nh + dbhh[2*HH + j]));
                float hprev = buf[b*XST + 384 + j];
                float h2 = (1.0f - z)*n + z*hprev;
                g_h[(t+1) & 1][b*HH + j] = h2;
                g_hT[j*32 + b] = h2;          // transposed copy for P2
            }
        }
        gbar(nbar);

        // -------- P2: logits+argmax (c<NLC, warp-tile tw=c*8+w) || attn (c>=NLC) --------
        if (c < NLC) {
            const int tw = c*8 + w;
            const bool active = (tw < 1000);
            const int vi = lane >> 2, bi = lane & 3;
            const int vlane = tw*32 + vi*4;

            if (tid < BB) slots[tid] = 0ULL;
            // identity copy of pre-transposed h: [k][b] stride 32, 128B-aligned rows
            {
                const float4* src = (const float4*)g_hT;
                float4* dst = (float4*)buf;
                #pragma unroll
                for (int i = 0; i < 8; i++) dst[tid + i*256] = src[tid + i*256];
            }

            if (active) {
                const float* wp = g_oWT + vlane;
                // cold-start loads overlap staging latency
                float4 wreg[8];
                #pragma unroll
                for (int i = 0; i < 8; i++) wreg[i] = *(const float4*)(wp + (size_t)i*VV);
                float4 b4 = *(const float4*)(ob + vlane);
                __syncthreads();

                ull acc[4][4];
                acc[0][0]=acc[0][1]=acc[0][2]=acc[0][3]=pk2(b4.x, b4.x);
                acc[1][0]=acc[1][1]=acc[1][2]=acc[1][3]=pk2(b4.y, b4.y);
                acc[2][0]=acc[2][1]=acc[2][2]=acc[2][3]=pk2(b4.z, b4.z);
                acc[3][0]=acc[3][1]=acc[3][2]=acc[3][3]=pk2(b4.w, b4.w);

                for (int k8 = 0; k8 < 32; k8++) {
                    float4 wnext[8];
                    if (k8 < 31) {
                        #pragma unroll
                        for (int i = 0; i < 8; i++)
                            wnext[i] = *(const float4*)(wp + (size_t)(k8*8 + 8 + i)*VV);
                    }
                    #pragma unroll
                    for (int i = 0; i < 8; i++) {
                        int k = k8*8 + i;
                        const ulonglong2* hp = (const ulonglong2*)(buf + k*32 + bi*8);
                        ulonglong2 h01 = hp[0];
                        ulonglong2 h23 = hp[1];
                        ull W;
                        W = pk2(wreg[i].x, wreg[i].x);
                        acc[0][0]=fma2(W,h01.x,acc[0][0]); acc[0][1]=fma2(W,h01.y,acc[0][1]);
                        acc[0][2]=fma2(W,h23.x,acc[0][2]); acc[0][3]=fma2(W,h23.y,acc[0][3]);
                        W = pk2(wreg[i].y, wreg[i].y);
                        acc[1][0]=fma2(W,h01.x,acc[1][0]); acc[1][1]=fma2(W,h01.y,acc[1][1]);
                        acc[1][2]=fma2(W,h23.x,acc[1][2]); acc[1][3]=fma2(W,h23.y,acc[1][3]);
                        W = pk2(wreg[i].z, wreg[i].z);
                        acc[2][0]=fma2(W,h01.x,acc[2][0]); acc[2][1]=fma2(W,h01.y,acc[2][1]);
                        acc[2][2]=fma2(W,h23.x,acc[2][2]); acc[2][3]=fma2(W,h23.y,acc[2][3]);
                        W = pk2(wreg[i].w, wreg[i].w);
                        acc[3][0]=fma2(W,h01.x,acc[3][0]); acc[3][1]=fma2(W,h01.y,acc[3][1]);
                        acc[3][2]=fma2(W,h23.x,acc[3][2]); acc[3][3]=fma2(W,h23.y,acc[3][3]);
                    }
                    if (k8 < 31) {
                        #pragma unroll
                        for (int i = 0; i < 8; i++) wreg[i] = wnext[i];
                    }
                }

                float f[4][8];
                #pragma unroll
                for (int v = 0; v < 4; v++) {
                    #pragma unroll
                    for (int bp = 0; bp < 4; bp++)
                        upk2(acc[v][bp], f[v][2*bp], f[v][2*bp+1]);
                }
                float* outp = out + (size_t)t*VV;
                #pragma unroll
                for (int j = 0; j < 8; j++) {
                    int b = bi*8 + j;
                    *(float4*)(outp + (size_t)b*TV + vlane) =
                        make_float4(f[0][j], f[1][j], f[2][j], f[3][j]);
                    unsigned bk = fkey(f[0][j]); unsigned bv = (unsigned)vlane;
                    #pragma unroll
                    for (int v = 1; v < 4; v++) {
                        unsigned kk = fkey(f[v][j]);
                        if (kk > bk) { bk = kk; bv = (unsigned)(vlane + v); }
                    }
                    ull kv = ((ull)bk << 32) | (ull)(0xFFFFFFFFu - bv);
                    #pragma unroll
                    for (int o = 4; o < 32; o <<= 1) {
                        ull other = __shfl_xor_sync(0xffffffffu, kv, o);
                        if (other > kv) kv = other;
                    }
                    if (vi == 0) atomicMax(&slots[b], kv);
                }
            } else {
                __syncthreads();   // match active warps' post-staging barrier
            }
            __syncthreads();
            if (tid < BB) atomicMax(&g_amax[t & 1][tid], slots[tid]);
        } else if (t < TT-1) {
            do_attn(g_h[(t+1) & 1]);
        }
        gbar(nbar);
    }
}

extern "C" void kernel_launch(void* const* d_in, const int* in_sizes, int n_in,
                              void* d_out, int out_size) {
    const int*   ing      = (const int*)d_in[0];
    const float* emb      = (const float*)d_in[1];
    const float* enc_Wih  = (const float*)d_in[2];
    const float* enc_Whh  = (const float*)d_in[3];
    const float* enc_bih  = (const float*)d_in[4];
    const float* enc_bhh  = (const float*)d_in[5];
    const float* dec_Wih  = (const float*)d_in[6];
    const float* dec_Whh  = (const float*)d_in[7];
    const float* dec_bih  = (const float*)d_in[8];
    const float* dec_bhh  = (const float*)d_in[9];
    const float* attn_W   = (const float*)d_in[10];
    const float* attn_b   = (const float*)d_in[11];
    const float* out_W    = (const float*)d_in[12];
    const float* out_b    = (const float*)d_in[13];
    float* out = (float*)d_out;

    static int configured = 0;
    if (!configured) {
        cudaFuncSetAttribute(mega, cudaFuncAttributeMaxDynamicSharedMemorySize, 197632);
        configured = 1;
    }
    k_reset<<<1, 1>>>();
    mega<<<GRIDN, 256, 197632>>>(ing, emb, enc_Wih, enc_Whh, enc_bih, enc_bhh,
                                 dec_Wih, dec_Whh, dec_bih, dec_bhh,
                                 attn_W, attn_b, out_W, out_b, out);
}

// round 17
// speedup vs baseline: 1.0326x; 1.0326x over previous
#include <cuda_runtime.h>
#include <cuda_bf16.h>
#include <cstdint>

#define BB 32
#define SS 100
#define TT 100
#define EE 128
#define HH 256
#define VV 32000
#define G3 (3*HH)
#define TV (TT*VV)
#define GRIDN 148
#define BST 36      // Xih staging stride (setup only)
#define XST 649     // P1 x staging stride [b][k]
#define EST 193     // encoder weight smem stride

typedef unsigned long long ull;

__device__ float g_Xih[BB*SS*G3];
__device__ float g_enc_outs[BB*SS*HH];
__device__ float g_enc_part[BB*SS];
__device__ float g_h[2][BB*HH];
__device__ float g_hT[HH*BB];            // h transposed [j][b], written by P1
__device__ float g_hx[BB*HH];
__device__ float g_ctx[BB*HH];
__device__ ull g_amax[2][BB];
__device__ unsigned g_ctr;
__device__ unsigned g_ectr[BB];
__device__ float g_oWT[(size_t)HH*VV];
__device__ float g_eWihT[EE*G3];

__device__ __forceinline__ float sigf(float x) { return 1.0f / (1.0f + expf(-x)); }
__device__ __forceinline__ unsigned fkey(float f) {
    unsigned u = __float_as_uint(f);
    return (u & 0x80000000u) ? ~u : (u | 0x80000000u);
}
__device__ __forceinline__ ull pk2(float x, float y) {
    ull r; asm("mov.b64 %0, {%1, %2};" : "=l"(r) : "f"(x), "f"(y)); return r;
}
__device__ __forceinline__ void upk2(ull p, float &x, float &y) {
    asm("mov.b64 {%0, %1}, %2;" : "=f"(x), "=f"(y) : "l"(p));
}
__device__ __forceinline__ ull fma2(ull a, ull b, ull c) {
    ull d; asm("fma.rn.f32x2 %0, %1, %2, %3;" : "=l"(d) : "l"(a), "l"(b), "l"(c)); return d;
}

// grid barrier: tight poll first, nanosleep backoff later
__device__ __forceinline__ void gbar(int &nbar) {
    __syncthreads();
    if (threadIdx.x == 0) {
        __threadfence();
        unsigned tgt = (unsigned)(nbar + 1) * GRIDN;
        atomicAdd(&g_ctr, 1u);
        unsigned iter = 0;
        while (true) {
            unsigned v;
            asm volatile("ld.acquire.gpu.global.u32 %0, [%1];" : "=r"(v) : "l"(&g_ctr));
            if (v >= tgt) break;
            ++iter;
            if (iter > 8000000u) break;
            if (iter > 2048u) __nanosleep(64);
        }
        __threadfence();
    }
    nbar++;
    __syncthreads();
}

__device__ __forceinline__ void minibar(int grp, int step) {
    __syncthreads();
    if (threadIdx.x == 0) {
        __threadfence();
        unsigned tgt = (unsigned)(step + 1) * 4u;
        atomicAdd(&g_ectr[grp], 1u);
        unsigned iter = 0;
        while (true) {
            unsigned v;
            asm volatile("ld.acquire.gpu.global.u32 %0, [%1];" : "=r"(v) : "l"(&g_ectr[grp]));
            if (v >= tgt) break;
            if (++iter > 20000000u) break;
        }
        __threadfence();
    }
    __syncthreads();
}

__global__ void k_reset() {
    g_ctr = 0u;
    for (int i = 0; i < BB; i++) g_ectr[i] = 0u;
}

__device__ __forceinline__ float rsum256(float v, float* red) {
    int tid = threadIdx.x;
    red[tid] = v; __syncthreads();
    #pragma unroll
    for (int o = 128; o > 0; o >>= 1) { if (tid < o) red[tid] += red[tid + o]; __syncthreads(); }
    float r = red[0]; __syncthreads();
    return r;
}
__device__ __forceinline__ float rmax256(float v, float* red) {
    int tid = threadIdx.x;
    red[tid] = v; __syncthreads();
    #pragma unroll
    for (int o = 128; o > 0; o >>= 1) { if (tid < o) red[tid] = fmaxf(red[tid], red[tid + o]); __syncthreads(); }
    float r = red[0]; __syncthreads();
    return r;
}

__global__ void __launch_bounds__(256, 1)
mega(const int* __restrict__ ing, const float* __restrict__ emb,
     const float* __restrict__ eWih, const float* __restrict__ eWhh,
     const float* __restrict__ ebih, const float* __restrict__ ebhh,
     const float* __restrict__ dWih, const float* __restrict__ dWhh,
     const float* __restrict__ dbih, const float* __restrict__ dbhh,
     const float* __restrict__ aW, const float* __restrict__ ab,
     const float* __restrict__ oW, const float* __restrict__ ob,
     float* __restrict__ out)
{
    extern __shared__ float dyn[];
    float* wsm = dyn;
    float* buf = dyn + 3840;   // 128B-aligned

    __shared__ float S[8][2][32];
    __shared__ float S4[4][3][64];
    __shared__ float hs[HH];
    __shared__ float ebs[192];
    __shared__ float red[256];
    __shared__ float ws[128];
    __shared__ int   toks[BB];
    __shared__ ull   slots[BB];

    const int c = blockIdx.x, tid = threadIdx.x;
    const int w = tid >> 5, lane = tid & 31;
    const int tx = tid & 31, ty = tid >> 5;
    int nbar = 0;

    // ============ Phase A: zero h0 + transposes (oW, eWih) ============
    if (c == 0) for (int i = tid; i < BB*HH; i += 256) g_h[0][i] = 0.0f;
    {
        float* tbuf = buf;
        for (int tile = c; tile < 8096; tile += GRIDN) {
            __syncthreads();
            if (tile < 8000) {
                int vt = tile >> 3, kt = tile & 7;
                int v0 = vt*32, k0 = kt*32;
                #pragma unroll
                for (int i = 0; i < 4; i++) {
                    int vv = ty + 8*i;
                    tbuf[vv*33 + tx] = oW[(size_t)(v0+vv)*HH + k0 + tx];
                }
                __syncthreads();
                #pragma unroll
                for (int i = 0; i < 4; i++) {
                    int kk = ty + 8*i;
                    g_oWT[(size_t)(k0+kk)*VV + v0 + tx] = tbuf[tx*33 + kk];
                }
            } else {
                int tt = tile - 8000;
                int rt = tt >> 2, kt = tt & 3;
                int r0 = rt*32, k0 = kt*32;
                #pragma unroll
                for (int i = 0; i < 4; i++) {
                    int rr = ty + 8*i;
                    tbuf[rr*33 + tx] = eWih[(size_t)(r0+rr)*EE + k0 + tx];
                }
                __syncthreads();
                #pragma unroll
                for (int i = 0; i < 4; i++) {
                    int kk = ty + 8*i;
                    g_eWihT[(k0+kk)*G3 + r0 + tx] = tbuf[tx*33 + kk];
                }
            }
        }
    }
    gbar(nbar);

    // ============ Phase B: Xih GEMM (c<100) + encoder weights (c<128) ============
    if (c < 100) {
        int p0 = c*32;
        if (tid < 32) toks[tid] = ing[p0 + tid];
        __syncthreads();
        for (int idx = tid; idx < EE*32; idx += 256) {
            int p = idx >> 7, k = idx & 127;
            buf[k*BST + p] = emb[(size_t)toks[p]*EE + k];
        }
        __syncthreads();
        ull acc[3][16];
        #pragma unroll
        for (int g = 0; g < 3; g++) {
            float bi = ebih[tid + g*256];
            ull bv = pk2(bi, bi);
            #pragma unroll
            for (int j = 0; j < 16; j++) acc[g][j] = bv;
        }
        #pragma unroll 2
        for (int k = 0; k < EE; k++) {
            float w0 = g_eWihT[k*G3 + tid];
            float w1 = g_eWihT[k*G3 + 256 + tid];
            float w2 = g_eWihT[k*G3 + 512 + tid];
            ull W0 = pk2(w0, w0), W1 = pk2(w1, w1), W2 = pk2(w2, w2);
            const ulonglong2* xp = (const ulonglong2*)(buf + k*BST);
            #pragma unroll
            for (int i = 0; i < 8; i++) {
                ulonglong2 hv = xp[i];
                acc[0][2*i]   = fma2(W0, hv.x, acc[0][2*i]);
                acc[0][2*i+1] = fma2(W0, hv.y, acc[0][2*i+1]);
                acc[1][2*i]   = fma2(W1, hv.x, acc[1][2*i]);
                acc[1][2*i+1] = fma2(W1, hv.y, acc[1][2*i+1]);
                acc[2][2*i]   = fma2(W2, hv.x, acc[2][2*i]);
                acc[2][2*i+1] = fma2(W2, hv.y, acc[2][2*i+1]);
            }
        }
        #pragma unroll
        for (int g = 0; g < 3; g++) {
            int r = tid + g*256;
            #pragma unroll
            for (int j = 0; j < 16; j++) {
                float f0, f1;
                upk2(acc[g][j], f0, f1);
                g_Xih[(size_t)(p0 + 2*j)*G3 + r] = f0;
                g_Xih[(size_t)(p0 + 2*j + 1)*G3 + r] = f1;
            }
        }
    }
    __syncthreads();
    if (c < 128) {
        int part = c & 3;
        for (int idx = tid; idx < 192*64; idx += 256) {
            int k4 = idx & 63, r = idx >> 6;
            int g = r >> 6, jl = r & 63;
            float4 v = *(const float4*)(eWhh + (size_t)(g*256 + part*64 + jl)*HH + 4*k4);
            wsm[(4*k4+0)*EST + r] = v.x;
            wsm[(4*k4+1)*EST + r] = v.y;
            wsm[(4*k4+2)*EST + r] = v.z;
            wsm[(4*k4+3)*EST + r] = v.w;
        }
        for (int i = tid; i < 192; i += 256) {
            int g = i >> 6, jl = i & 63;
            ebs[i] = ebhh[g*256 + part*64 + jl];
        }
        if (tid < HH) hs[tid] = 0.0f;
    }
    gbar(nbar);

    // ============ Encoder: 32 groups x 4 CTAs ============
    if (c < 128) {
        int b = c >> 2, part = c & 3;
        for (int s = 0; s < SS; s++) {
            int jl = tid & 63, q = tid >> 6;
            float aR = 0.f, aZ = 0.f, aN = 0.f;
            const float* wp = wsm + (q*64)*EST;
            #pragma unroll 4
            for (int kk = 0; kk < 64; kk++) {
                float hv = hs[q*64 + kk];
                aR += wp[kk*EST + jl] * hv;
                aZ += wp[kk*EST + 64 + jl] * hv;
                aN += wp[kk*EST + 128 + jl] * hv;
            }
            S4[q][0][jl] = aR; S4[q][1][jl] = aZ; S4[q][2][jl] = aN;
            __syncthreads();
            if (tid < 64) {
                int j = part*64 + tid;
                float rs = S4[0][0][tid]+S4[1][0][tid]+S4[2][0][tid]+S4[3][0][tid];
                float zs = S4[0][1][tid]+S4[1][1][tid]+S4[2][1][tid]+S4[3][1][tid];
                float ns = S4[0][2][tid]+S4[1][2][tid]+S4[2][2][tid]+S4[3][2][tid];
                const float* gi = g_Xih + ((size_t)b*SS + s)*G3;
                float r = sigf(gi[j] + rs + ebs[tid]);
                float z = sigf(gi[HH + j] + zs + ebs[64 + tid]);
                float n = tanhf(gi[2*HH + j] + r*(ns + ebs[128 + tid]));
                float h2 = (1.0f - z)*n + z*hs[j];
                g_enc_outs[((size_t)b*SS + s)*HH + j] = h2;
                g_hx[b*HH + j] = h2;
                if (s == SS-1) g_h[0][b*HH + j] = h2;
            }
            minibar(b, s);
            if (tid < HH) hs[tid] = g_hx[b*HH + tid];
            __syncthreads();
        }
    }
    gbar(nbar);

    // ============ enc_part + decoder weight slice ============
    if (c < 128) {
        int j0 = 2*c;
        for (int g = tid; g < 3840; g += 256) {
            int jl = (g >= 1920) ? 1 : 0;
            int gg = g - jl*1920;
            int j = j0 + jl;
            int rl, k;
            if (gg < 640)       { rl = 0; k = gg; }
            else if (gg < 1280) { rl = 1; k = gg - 640; }
            else if (gg < 1664) { rl = 2; k = gg - 1280; }
            else                { rl = 3; k = gg - 1664; }
            float v;
            if (rl == 0)      v = (k < 384) ? dWih[(size_t)j*384 + k]          : dWhh[(size_t)j*HH + (k-384)];
            else if (rl == 1) v = (k < 384) ? dWih[(size_t)(256+j)*384 + k]    : dWhh[(size_t)(256+j)*HH + (k-384)];
            else if (rl == 2) v = dWih[(size_t)(512+j)*384 + k];
            else              v = dWhh[(size_t)(512+j)*HH + k];
            wsm[g] = v;
        }
    }
    {
        int gt = c*256 + tid;
        if (gt < BB*SS) {
            const float4* e4 = (const float4*)(g_enc_outs + (size_t)gt*HH);
            const float4* w4 = (const float4*)aW;
            float a0 = ab[0], a1=0,a2=0,a3=0;
            #pragma unroll 8
            for (int k = 0; k < HH/4; k++) {
                float4 e = e4[k]; float4 ww = __ldg(&w4[k]);
                a0 += e.x*ww.x; a1 += e.y*ww.y; a2 += e.z*ww.z; a3 += e.w*ww.w;
            }
            g_enc_part[gt] = (a0+a1)+(a2+a3);
        }
    }
    gbar(nbar);

    // ============ decoder ============
    static const int rowoff_[8] = {0,640,1280,1664,1920,2560,3200,3584};
    static const int s0row_[8] = {0,0,1,2,4,4,5,6};
    static const int s0k_[8]   = {0,480,320,160,0,480,320,160};
    static const int s0len_[8] = {480,160,320,224,480,160,320,224};
    static const int s1row_[8] = {0,1,2,3,4,5,6,7};
    static const int s1len_[8] = {0,320,160,256,0,320,160,256};

    auto do_attn = [&](const float* h) {
        int i = c - 125;
        int nb = (i + 23 < BB) ? 2 : 1;
        for (int q = 0; q < nb; q++) {
            int b = i + q*23;
            float p = h[b*HH + tid] * aW[HH + tid];
            float hw = rsum256(p, red);
            float sc = (tid < SS) ? (g_enc_part[b*SS + tid] + hw) : -1e30f;
            float mx = rmax256(sc, red);
            float e = (tid < SS) ? expf(sc - mx) : 0.0f;
            if (tid < 128) ws[tid] = (tid < SS) ? e : 0.0f;
            float inv = 1.0f / rsum256(e, red);
            __syncthreads();
            int j = tid;
            const float* eo = g_enc_outs + (size_t)b*SS*HH + j;
            float a0=0, a1=0;
            #pragma unroll 4
            for (int s = 0; s < SS; s += 2) {
                a0 += ws[s] * eo[(size_t)s*HH];
                a1 += ws[s+1] * eo[(size_t)(s+1)*HH];
            }
            g_ctx[b*HH + j] = (a0 + a1) * inv;
            __syncthreads();
        }
    };

    if (c >= 125) do_attn(g_h[0]);
    gbar(nbar);

    for (int t = 0; t < TT; t++) {
        // -------- P1: GRU (c<128) --------
        if (c < 128) {
            if (tid < BB)
                toks[tid] = (t == 0) ? 1
                    : (int)(0xFFFFFFFFu - (unsigned)(g_amax[(t-1) & 1][tid] & 0xFFFFFFFFull));
            if (c == 0 && tid >= 32 && tid < 64) g_amax[t & 1][tid - 32] = 0ULL;
            __syncthreads();
            const float* hin = g_h[t & 1];
            {
                int b = tid >> 3, f = tid & 7;
                float* xr = buf + b*XST;
                #pragma unroll
                for (int i = 0; i < 4; i++) {
                    int k4 = f + 8*i;
                    float4 v = *(const float4*)(emb + (size_t)toks[b]*EE + 4*k4);
                    xr[4*k4+0]=v.x; xr[4*k4+1]=v.y; xr[4*k4+2]=v.z; xr[4*k4+3]=v.w;
                }
                #pragma unroll
                for (int i = 0; i < 8; i++) {
                    int k4 = f + 8*i;
                    float4 v = *(const float4*)(g_ctx + b*HH + 4*k4);
                    int o = 128 + 4*k4;
                    xr[o]=v.x; xr[o+1]=v.y; xr[o+2]=v.z; xr[o+3]=v.w;
                }
                #pragma unroll
                for (int i = 0; i < 8; i++) {
                    int k4 = f + 8*i;
                    float4 v = *(const float4*)(hin + b*HH + 4*k4);
                    int o = 384 + 4*k4;
                    xr[o]=v.x; xr[o+1]=v.y; xr[o+2]=v.z; xr[o+3]=v.w;
                }
            }
            __syncthreads();
            const float* xb = buf + lane*XST;
            {
                int r0 = s0row_[w], k0 = s0k_[w], l0 = s0len_[w];
                const float4* wv = (const float4*)(wsm + rowoff_[r0] + k0);
                int bo = (((r0 & 3) == 3) ? 384 : 0) + k0;
                float a0=0,a1=0,a2=0,a3=0;
                #pragma unroll 4
                for (int i = 0; i < l0/4; i++) {
                    float4 x = wv[i];
                    const float* xp = xb + bo + 4*i;
                    a0 += x.x*xp[0]; a1 += x.y*xp[1];
                    a2 += x.z*xp[2]; a3 += x.w*xp[3];
                }
                S[w][0][lane] = (a0+a1)+(a2+a3);
            }
            {
                int r1 = s1row_[w], l1 = s1len_[w];
                float acc = 0.0f;
                if (l1 > 0) {
                    const float4* wv = (const float4*)(wsm + rowoff_[r1]);
                    int bo = ((r1 & 3) == 3) ? 384 : 0;
                    float a0=0,a1=0,a2=0,a3=0;
                    #pragma unroll 4
                    for (int i = 0; i < l1/4; i++) {
                        float4 x = wv[i];
                        const float* xp = xb + bo + 4*i;
                        a0 += x.x*xp[0]; a1 += x.y*xp[1];
                        a2 += x.z*xp[2]; a3 += x.w*xp[3];
                    }
                    acc = (a0+a1)+(a2+a3);
                }
                S[w][1][lane] = acc;
            }
            __syncthreads();
            if (w == 0 || w == 4) {
                int jl = w >> 2, base = jl*4;
                int j = 2*c + jl, b = lane;
                float r_in = S[base+0][0][b] + S[base+1][0][b];
                float z_in = S[base+1][1][b] + S[base+2][0][b];
                float nx   = S[base+2][1][b] + S[base+3][0][b];
                float nh   = S[base+3][1][b];
                float r = sigf(r_in + dbih[j] + dbhh[j]);
                float z = sigf(z_in + dbih[HH + j] + dbhh[HH + j]);
                float n = tanhf(nx + dbih[2*HH + j] + r*(nh + dbhh[2*HH + j]));
                float hprev = buf[b*XST + 384 + j];
                float h2 = (1.0f - z)*n + z*hprev;
                g_h[(t+1) & 1][b*HH + j] = h2;
                g_hT[j*32 + b] = h2;          // transposed copy for P2
            }
        }
        gbar(nbar);

        // -------- P2: logits+argmax (c<125) || attn (c>=125) --------
        if (c < 125) {
            const int vi = lane >> 2, bi = lane & 3;
            const int vlane = c*256 + w*32 + vi*4;
            const float* wp = g_oWT + vlane;

            // cold-start: preload k-blocks 0 and 1 (distance-2 pipeline) + bias
            float4 wA[8], wB[8];
            #pragma unroll
            for (int i = 0; i < 8; i++) wA[i] = *(const float4*)(wp + (size_t)i*VV);
            #pragma unroll
            for (int i = 0; i < 8; i++) wB[i] = *(const float4*)(wp + (size_t)(8+i)*VV);
            float4 b4 = *(const float4*)(ob + vlane);

            if (tid < BB) slots[tid] = 0ULL;
            // identity copy of pre-transposed h: [k][b] stride 32, 128B-aligned rows
            {
                const float4* src = (const float4*)g_hT;
                float4* dst = (float4*)buf;
                #pragma unroll
                for (int i = 0; i < 8; i++) dst[tid + i*256] = src[tid + i*256];
            }
            __syncthreads();

            ull acc[4][4];
            acc[0][0]=acc[0][1]=acc[0][2]=acc[0][3]=pk2(b4.x, b4.x);
            acc[1][0]=acc[1][1]=acc[1][2]=acc[1][3]=pk2(b4.y, b4.y);
            acc[2][0]=acc[2][1]=acc[2][2]=acc[2][3]=pk2(b4.z, b4.z);
            acc[3][0]=acc[3][1]=acc[3][2]=acc[3][3]=pk2(b4.w, b4.w);

            // compute block over 8 consecutive k starting at k0 with weights WR
            auto cblock = [&](const float4* WR, int k0) {
                #pragma unroll
                for (int i = 0; i < 8; i++) {
                    int k = k0 + i;
                    const ulonglong2* hp = (const ulonglong2*)(buf + k*32 + bi*8);
                    ulonglong2 h01 = hp[0];
                    ulonglong2 h23 = hp[1];
                    ull W;
                    W = pk2(WR[i].x, WR[i].x);
                    acc[0][0]=fma2(W,h01.x,acc[0][0]); acc[0][1]=fma2(W,h01.y,acc[0][1]);
                    acc[0][2]=fma2(W,h23.x,acc[0][2]); acc[0][3]=fma2(W,h23.y,acc[0][3]);
                    W = pk2(WR[i].y, WR[i].y);
                    acc[1][0]=fma2(W,h01.x,acc[1][0]); acc[1][1]=fma2(W,h01.y,acc[1][1]);
                    acc[1][2]=fma2(W,h23.x,acc[1][2]); acc[1][3]=fma2(W,h23.y,acc[1][3]);
                    W = pk2(WR[i].z, WR[i].z);
                    acc[2][0]=fma2(W,h01.x,acc[2][0]); acc[2][1]=fma2(W,h01.y,acc[2][1]);
                    acc[2][2]=fma2(W,h23.x,acc[2][2]); acc[2][3]=fma2(W,h23.y,acc[2][3]);
                    W = pk2(WR[i].w, WR[i].w);
                    acc[3][0]=fma2(W,h01.x,acc[3][0]); acc[3][1]=fma2(W,h01.y,acc[3][1]);
                    acc[3][2]=fma2(W,h23.x,acc[3][2]); acc[3][3]=fma2(W,h23.y,acc[3][3]);
                }
            };

            // distance-2 pipelined k loop: 16 k per iteration
            for (int k16 = 0; k16 < 256; k16 += 16) {
                float4 nA[8], nB[8];
                if (k16 < 240) {
                    #pragma unroll
                    for (int i = 0; i < 8; i++)
                        nA[i] = *(const float4*)(wp + (size_t)(k16 + 16 + i)*VV);
                }
                cblock(wA, k16);
                if (k16 < 240) {
                    #pragma unroll
                    for (int i = 0; i < 8; i++)
                        nB[i] = *(const float4*)(wp + (size_t)(k16 + 24 + i)*VV);
                }
                cblock(wB, k16 + 8);
                if (k16 < 240) {
                    #pragma unroll
                    for (int i = 0; i < 8; i++) { wA[i] = nA[i]; wB[i] = nB[i]; }
                }
            }

            float f[4][8];
            #pragma unroll
            for (int v = 0; v < 4; v++) {
                #pragma unroll
                for (int bp = 0; bp < 4; bp++)
                    upk2(acc[v][bp], f[v][2*bp], f[v][2*bp+1]);
            }
            float* outp = out + (size_t)t*VV;
            #pragma unroll
            for (int j = 0; j < 8; j++) {
                int b = bi*8 + j;
                *(float4*)(outp + (size_t)b*TV + vlane) =
                    make_float4(f[0][j], f[1][j], f[2][j], f[3][j]);
                unsigned bk = fkey(f[0][j]); unsigned bv = (unsigned)vlane;
                #pragma unroll
                for (int v = 1; v < 4; v++) {
                    unsigned kk = fkey(f[v][j]);
                    if (kk > bk) { bk = kk; bv = (unsigned)(vlane + v); }
                }
                ull kv = ((ull)bk << 32) | (ull)(0xFFFFFFFFu - bv);
                #pragma unroll
                for (int o = 4; o < 32; o <<= 1) {
                    ull other = __shfl_xor_sync(0xffffffffu, kv, o);
                    if (other > kv) kv = other;
                }
                if (vi == 0) atomicMax(&slots[b], kv);
            }
            __syncthreads();
            if (tid < BB) atomicMax(&g_amax[t & 1][tid], slots[tid]);
        } else if (t < TT-1) {
            do_attn(g_h[(t+1) & 1]);
        }
        gbar(nbar);
    }
}

extern "C" void kernel_launch(void* const* d_in, const int* in_sizes, int n_in,
                              void* d_out, int out_size) {
    const int*   ing      = (const int*)d_in[0];
    const float* emb      = (const float*)d_in[1];
    const float* enc_Wih  = (const float*)d_in[2];
    const float* enc_Whh  = (const float*)d_in[3];
    const float* enc_bih  = (const float*)d_in[4];
    const float* enc_bhh  = (const float*)d_in[5];
    const float* dec_Wih  = (const float*)d_in[6];
    const float* dec_Whh  = (const float*)d_in[7];
    const float* dec_bih  = (const float*)d_in[8];
    const float* dec_bhh  = (const float*)d_in[9];
    const float* attn_W   = (const float*)d_in[10];
    const float* attn_b   = (const float*)d_in[11];
    const float* out_W    = (const float*)d_in[12];
    const float* out_b    = (const float*)d_in[13];
    float* out = (float*)d_out;

    static int configured = 0;
    if (!configured) {
        cudaFuncSetAttribute(mega, cudaFuncAttributeMaxDynamicSharedMemorySize, 197632);
        configured = 1;
    }
    k_reset<<<1, 1>>>();
    mega<<<GRIDN, 256, 197632>>>(ing, emb, enc_Wih, enc_Whh, enc_bih, enc_bhh,
                                 dec_Wih, dec_Whh, dec_bih, dec_bhh,
                                 attn_W, attn_b, out_W, out_b, out);
}